// round 2
// baseline (speedup 1.0000x reference)
#include <cuda_runtime.h>
#include <math.h>
#include <stdint.h>

#define D_MODEL 1024
#define NHEAD 16
#define HEAD_DIM 64
#define BATCH 2
#define SEQ 2048
#define NTOK (BATCH * SEQ)                         // 4096
#define OUT_ELEMS ((size_t)BATCH * SEQ * D_MODEL)  // 4194304
#define ATTN_ELEMS ((size_t)BATCH * NHEAD * SEQ * SEQ)  // 134217728
#define LN_EPS 1e-5f

// ---------------- scratch (device globals: no allocation allowed) ----------
__device__ float g_qn[NTOK * D_MODEL];
__device__ float g_kn[NTOK * D_MODEL];
__device__ float g_vn[NTOK * D_MODEL];
__device__ float g_q[NTOK * D_MODEL];
__device__ float g_k[NTOK * D_MODEL];
__device__ float g_v[NTOK * D_MODEL];
__device__ float g_ctx[NTOK * D_MODEL];
// fallback in case the harness output buffer only holds `out`
__device__ float g_attn_fb[ATTN_ELEMS];

// ---------------- LayerNorm: one block per row, 256 threads, float4 -------
__global__ void ln_kernel(const float* __restrict__ x,
                          const float* __restrict__ gamma,
                          const float* __restrict__ beta,
                          int which)  // 0->g_qn, 1->g_kn, 2->g_vn
{
    float* __restrict__ y = (which == 0) ? g_qn : (which == 1) ? g_kn : g_vn;
    int row = blockIdx.x;
    int tid = threadIdx.x;
    const float4* xr = (const float4*)(x + (size_t)row * D_MODEL);
    float4 v = xr[tid];

    float s  = v.x + v.y + v.z + v.w;
    float s2 = fmaf(v.x, v.x, fmaf(v.y, v.y, fmaf(v.z, v.z, v.w * v.w)));

    __shared__ float redA[8], redB[8];
    #pragma unroll
    for (int o = 16; o > 0; o >>= 1) {
        s  += __shfl_xor_sync(0xffffffffu, s, o);
        s2 += __shfl_xor_sync(0xffffffffu, s2, o);
    }
    int w = tid >> 5;
    if ((tid & 31) == 0) { redA[w] = s; redB[w] = s2; }
    __syncthreads();
    if (tid == 0) {
        float a = 0.f, b = 0.f;
        #pragma unroll
        for (int i = 0; i < 8; i++) { a += redA[i]; b += redB[i]; }
        redA[0] = a; redB[0] = b;
    }
    __syncthreads();
    float mean = redA[0] * (1.0f / D_MODEL);
    float var  = redB[0] * (1.0f / D_MODEL) - mean * mean;
    float inv  = rsqrtf(var + LN_EPS);

    float4 g = ((const float4*)gamma)[tid];
    float4 b = ((const float4*)beta)[tid];
    float4 o;
    o.x = (v.x - mean) * inv * g.x + b.x;
    o.y = (v.y - mean) * inv * g.y + b.y;
    o.z = (v.z - mean) * inv * g.z + b.z;
    o.w = (v.w - mean) * inv * g.w + b.w;
    ((float4*)(y + (size_t)row * D_MODEL))[tid] = o;
}

// ---------------- GEMM (NT): Y = X @ W^T + bias. M=4096, N=K=1024 ---------
// BM=BN=64, BK=16, 256 threads, 4x4 per thread.
__device__ __forceinline__ void gemm_nt_core(const float* __restrict__ X,
                                             const float* __restrict__ W,
                                             const float* __restrict__ bias,
                                             float* __restrict__ Y)
{
    __shared__ float As[16][64 + 4];
    __shared__ float Bs[16][64 + 4];
    int tid = threadIdx.x;
    int bn = blockIdx.x, bm = blockIdx.y;
    int ty = tid >> 4, tx = tid & 15;

    const float* Xb = X + (size_t)(bm * 64) * D_MODEL;
    const float* Wb = W + (size_t)(bn * 64) * D_MODEL;
    int lr = tid >> 2;           // 0..63
    int lc = (tid & 3) * 4;      // 0,4,8,12

    float acc[4][4] = {};
    for (int k0 = 0; k0 < D_MODEL; k0 += 16) {
        float4 xa = *(const float4*)(Xb + (size_t)lr * D_MODEL + k0 + lc);
        float4 wa = *(const float4*)(Wb + (size_t)lr * D_MODEL + k0 + lc);
        As[lc + 0][lr] = xa.x; As[lc + 1][lr] = xa.y;
        As[lc + 2][lr] = xa.z; As[lc + 3][lr] = xa.w;
        Bs[lc + 0][lr] = wa.x; Bs[lc + 1][lr] = wa.y;
        Bs[lc + 2][lr] = wa.z; Bs[lc + 3][lr] = wa.w;
        __syncthreads();
        #pragma unroll
        for (int k = 0; k < 16; k++) {
            float a[4], b[4];
            #pragma unroll
            for (int i = 0; i < 4; i++) a[i] = As[k][ty * 4 + i];
            #pragma unroll
            for (int j = 0; j < 4; j++) b[j] = Bs[k][tx * 4 + j];
            #pragma unroll
            for (int i = 0; i < 4; i++)
                #pragma unroll
                for (int j = 0; j < 4; j++)
                    acc[i][j] = fmaf(a[i], b[j], acc[i][j]);
        }
        __syncthreads();
    }
    #pragma unroll
    for (int i = 0; i < 4; i++) {
        int row = bm * 64 + ty * 4 + i;
        #pragma unroll
        for (int j = 0; j < 4; j++) {
            int col = bn * 64 + tx * 4 + j;
            Y[(size_t)row * D_MODEL + col] = acc[i][j] + bias[col];
        }
    }
}

// QKV projection: reads g_qn/g_kn/g_vn, writes g_q/g_k/g_v
__global__ void proj_kernel(const float* __restrict__ W,
                            const float* __restrict__ bias, int which)
{
    const float* X = (which == 0) ? g_qn : (which == 1) ? g_kn : g_vn;
    float* Y       = (which == 0) ? g_q  : (which == 1) ? g_k  : g_v;
    gemm_nt_core(X, W, bias, Y);
}

// Output projection: reads g_ctx, writes external out
__global__ void oproj_kernel(const float* __restrict__ W,
                             const float* __restrict__ bias,
                             float* __restrict__ out)
{
    gemm_nt_core(g_ctx, W, bias, out);
}

// ---------------- scores: logits = scale * Q K^T, causal-masked to 0 ------
// grid: (s_tile=32, t_tile=32, bh=32); 64x64 tile, K=64.
__global__ void scores_kernel(float* __restrict__ attn_ext)
{
    float* attn = attn_ext ? attn_ext : g_attn_fb;
    int bh = blockIdx.z;
    int b = bh >> 4, h = bh & 15;
    int bt = blockIdx.y, bs = blockIdx.x;
    int tid = threadIdx.x;

    float* out = attn + ((size_t)bh * SEQ + bt * 64) * SEQ + bs * 64;
    int lr = tid >> 4;            // 0..15
    int lc4 = (tid & 15) * 4;     // 0..60

    if (bs * 64 > bt * 64 + 63) {  // fully masked tile -> zeros
        float4 z = make_float4(0.f, 0.f, 0.f, 0.f);
        #pragma unroll
        for (int r = 0; r < 4; r++)
            *(float4*)(out + (size_t)(lr + r * 16) * SEQ + lc4) = z;
        return;
    }

    __shared__ float Qs[64][64 + 4];
    __shared__ float Ks[64][64 + 4];
    const float* Qb = g_q + ((size_t)(b * SEQ + bt * 64)) * D_MODEL + h * HEAD_DIM;
    const float* Kb = g_k + ((size_t)(b * SEQ + bs * 64)) * D_MODEL + h * HEAD_DIM;
    #pragma unroll
    for (int r = 0; r < 4; r++) {
        int m = lr + r * 16;
        float4 q4 = *(const float4*)(Qb + (size_t)m * D_MODEL + lc4);
        float4 k4 = *(const float4*)(Kb + (size_t)m * D_MODEL + lc4);
        Qs[m][lc4 + 0] = q4.x; Qs[m][lc4 + 1] = q4.y;
        Qs[m][lc4 + 2] = q4.z; Qs[m][lc4 + 3] = q4.w;
        Ks[m][lc4 + 0] = k4.x; Ks[m][lc4 + 1] = k4.y;
        Ks[m][lc4 + 2] = k4.z; Ks[m][lc4 + 3] = k4.w;
    }
    __syncthreads();

    int ty = tid >> 4, tx = tid & 15;
    float acc[4][4] = {};
    #pragma unroll 8
    for (int k = 0; k < 64; k++) {
        float a[4], c[4];
        #pragma unroll
        for (int i = 0; i < 4; i++) a[i] = Qs[ty * 4 + i][k];
        #pragma unroll
        for (int j = 0; j < 4; j++) c[j] = Ks[tx * 4 + j][k];
        #pragma unroll
        for (int i = 0; i < 4; i++)
            #pragma unroll
            for (int j = 0; j < 4; j++)
                acc[i][j] = fmaf(a[i], c[j], acc[i][j]);
    }
    const float scale = 0.125f;  // 64^-0.5
    #pragma unroll
    for (int i = 0; i < 4; i++) {
        int t = bt * 64 + ty * 4 + i;
        #pragma unroll
        for (int j = 0; j < 4; j++) {
            int s = bs * 64 + tx * 4 + j;
            out[(size_t)(ty * 4 + i) * SEQ + (tx * 4 + j)] =
                (s <= t) ? acc[i][j] * scale : 0.0f;
        }
    }
}

// ---------------- causal softmax: one block per (b,h,t) row ---------------
__global__ void softmax_kernel(float* __restrict__ attn_ext)
{
    float* attn = attn_ext ? attn_ext : g_attn_fb;
    int row = blockIdx.x;            // 0..65535
    int t = row & (SEQ - 1);
    int n = t + 1;
    float* p = attn + (size_t)row * SEQ;
    int tid = threadIdx.x;

    float vals[8];
    int cnt = 0;
    float m = -INFINITY;
    for (int i = tid; i < n; i += 256) {
        float x = p[i];
        vals[cnt++] = x;
        m = fmaxf(m, x);
    }
    __shared__ float redA[8], redB[8];
    #pragma unroll
    for (int o = 16; o > 0; o >>= 1) m = fmaxf(m, __shfl_xor_sync(0xffffffffu, m, o));
    int w = tid >> 5;
    if ((tid & 31) == 0) redA[w] = m;
    __syncthreads();
    if (tid == 0) {
        float mm = redA[0];
        #pragma unroll
        for (int i = 1; i < 8; i++) mm = fmaxf(mm, redA[i]);
        redA[0] = mm;
    }
    __syncthreads();
    m = redA[0];

    float s = 0.f;
    for (int j = 0; j < cnt; j++) { vals[j] = expf(vals[j] - m); s += vals[j]; }
    #pragma unroll
    for (int o = 16; o > 0; o >>= 1) s += __shfl_xor_sync(0xffffffffu, s, o);
    if ((tid & 31) == 0) redB[w] = s;
    __syncthreads();
    if (tid == 0) {
        float ss = 0.f;
        #pragma unroll
        for (int i = 0; i < 8; i++) ss += redB[i];
        redB[0] = ss;
    }
    __syncthreads();
    float inv = 1.0f / redB[0];

    cnt = 0;
    for (int i = tid; i < n; i += 256) p[i] = vals[cnt++] * inv;
}

// ---------------- AV: ctx[b,t,h*64+d] = sum_s attn * v ---------------------
// grid: (1, t_tile=32, bh=32); K loop over s tiles 0..bt (masked region is 0)
__global__ void av_kernel(const float* __restrict__ attn_ext)
{
    const float* attn = attn_ext ? attn_ext : g_attn_fb;
    int bh = blockIdx.z;
    int b = bh >> 4, h = bh & 15;
    int bt = blockIdx.y;
    int tid = threadIdx.x;

    __shared__ float As[64][64 + 4];  // attn[t][s]
    __shared__ float Vs[64][64 + 4];  // v[s][d]
    const float* Ab = attn + ((size_t)bh * SEQ + bt * 64) * SEQ;
    const float* Vb = g_v + (size_t)(b * SEQ) * D_MODEL + h * HEAD_DIM;

    int lr = tid >> 4, lc4 = (tid & 15) * 4;
    int ty = tid >> 4, tx = tid & 15;
    float acc[4][4] = {};

    for (int ks = 0; ks <= bt; ks++) {
        #pragma unroll
        for (int r = 0; r < 4; r++) {
            int m = lr + r * 16;
            float4 a4 = *(const float4*)(Ab + (size_t)m * SEQ + ks * 64 + lc4);
            float4 v4 = *(const float4*)(Vb + (size_t)(ks * 64 + m) * D_MODEL + lc4);
            As[m][lc4 + 0] = a4.x; As[m][lc4 + 1] = a4.y;
            As[m][lc4 + 2] = a4.z; As[m][lc4 + 3] = a4.w;
            Vs[m][lc4 + 0] = v4.x; Vs[m][lc4 + 1] = v4.y;
            Vs[m][lc4 + 2] = v4.z; Vs[m][lc4 + 3] = v4.w;
        }
        __syncthreads();
        #pragma unroll 8
        for (int k = 0; k < 64; k++) {
            float a[4], c[4];
            #pragma unroll
            for (int i = 0; i < 4; i++) a[i] = As[ty * 4 + i][k];
            #pragma unroll
            for (int j = 0; j < 4; j++) c[j] = Vs[k][tx * 4 + j];
            #pragma unroll
            for (int i = 0; i < 4; i++)
                #pragma unroll
                for (int j = 0; j < 4; j++)
                    acc[i][j] = fmaf(a[i], c[j], acc[i][j]);
        }
        __syncthreads();
    }
    #pragma unroll
    for (int i = 0; i < 4; i++) {
        int row = b * SEQ + bt * 64 + ty * 4 + i;
        #pragma unroll
        for (int j = 0; j < 4; j++) {
            int col = h * HEAD_DIM + tx * 4 + j;
            g_ctx[(size_t)row * D_MODEL + col] = acc[i][j];
        }
    }
}

// ---------------- launch ---------------------------------------------------
extern "C" void kernel_launch(void* const* d_in, const int* in_sizes, int n_in,
                              void* d_out, int out_size)
{
    const float* query = (const float*)d_in[0];
    const float* key_  = (const float*)d_in[1];
    const float* value = (const float*)d_in[2];
    const float* Wq = (const float*)d_in[3];
    const float* bq = (const float*)d_in[4];
    const float* Wk = (const float*)d_in[5];
    const float* bk = (const float*)d_in[6];
    const float* Wv = (const float*)d_in[7];
    const float* bv = (const float*)d_in[8];
    const float* Wo = (const float*)d_in[9];
    const float* bo = (const float*)d_in[10];
    const float* ln_g = (const float*)d_in[11];
    const float* ln_b = (const float*)d_in[12];

    float* out = (float*)d_out;
    // reference returns (out, attn): attn follows out in the flattened output
    float* attn = ((size_t)out_size >= OUT_ELEMS + ATTN_ELEMS)
                      ? out + OUT_ELEMS : nullptr;

    // 1. shared LayerNorm on q/k/v inputs
    ln_kernel<<<NTOK, 256>>>(query, ln_g, ln_b, 0);
    ln_kernel<<<NTOK, 256>>>(key_,  ln_g, ln_b, 1);
    ln_kernel<<<NTOK, 256>>>(value, ln_g, ln_b, 2);

    // 2. Q/K/V projections
    dim3 pg(D_MODEL / 64, NTOK / 64);
    proj_kernel<<<pg, 256>>>(Wq, bq, 0);
    proj_kernel<<<pg, 256>>>(Wk, bk, 1);
    proj_kernel<<<pg, 256>>>(Wv, bv, 2);

    // 3. scores (masked logits, zeros above diagonal)
    scores_kernel<<<dim3(SEQ / 64, SEQ / 64, BATCH * NHEAD), 256>>>(attn);

    // 4. causal softmax (in-place over valid region)
    softmax_kernel<<<BATCH * NHEAD * SEQ, 256>>>(attn);

    // 5. attn @ V -> ctx
    av_kernel<<<dim3(1, SEQ / 64, BATCH * NHEAD), 256>>>(attn);

    // 6. output projection
    oproj_kernel<<<pg, 256>>>(Wo, bo, out);
}

// round 3
// speedup vs baseline: 1.1143x; 1.1143x over previous
#include <cuda_runtime.h>
#include <math.h>
#include <stdint.h>

#define D_MODEL 1024
#define NHEAD 16
#define HEAD_DIM 64
#define BATCH 2
#define SEQ 2048
#define NTOK (BATCH * SEQ)                         // 4096
#define OUT_ELEMS ((size_t)BATCH * SEQ * D_MODEL)  // 4194304
#define ATTN_ELEMS ((size_t)BATCH * NHEAD * SEQ * SEQ)  // 134217728
#define LN_EPS 1e-5f

// ---------------- scratch (device globals: no allocation allowed) ----------
__device__ float g_qn[NTOK * D_MODEL];
__device__ float g_kn[NTOK * D_MODEL];
__device__ float g_vn[NTOK * D_MODEL];
__device__ float g_q[NTOK * D_MODEL];
__device__ float g_k[NTOK * D_MODEL];
__device__ float g_v[NTOK * D_MODEL];
__device__ float g_ctx[NTOK * D_MODEL];
__device__ float g_attn_fb[ATTN_ELEMS];

// ---------------- LayerNorm: one block per row, 256 threads, float4 -------
__global__ void ln_kernel(const float* __restrict__ q_in,
                          const float* __restrict__ k_in,
                          const float* __restrict__ v_in,
                          const float* __restrict__ gamma,
                          const float* __restrict__ beta)
{
    int which = blockIdx.y;
    const float* x = (which == 0) ? q_in : (which == 1) ? k_in : v_in;
    float* __restrict__ y = (which == 0) ? g_qn : (which == 1) ? g_kn : g_vn;
    int row = blockIdx.x;
    int tid = threadIdx.x;
    const float4* xr = (const float4*)(x + (size_t)row * D_MODEL);
    float4 v = xr[tid];

    float s  = v.x + v.y + v.z + v.w;
    float s2 = fmaf(v.x, v.x, fmaf(v.y, v.y, fmaf(v.z, v.z, v.w * v.w)));

    __shared__ float redA[8], redB[8];
    #pragma unroll
    for (int o = 16; o > 0; o >>= 1) {
        s  += __shfl_xor_sync(0xffffffffu, s, o);
        s2 += __shfl_xor_sync(0xffffffffu, s2, o);
    }
    int w = tid >> 5;
    if ((tid & 31) == 0) { redA[w] = s; redB[w] = s2; }
    __syncthreads();
    if (tid == 0) {
        float a = 0.f, b = 0.f;
        #pragma unroll
        for (int i = 0; i < 8; i++) { a += redA[i]; b += redB[i]; }
        redA[0] = a; redB[0] = b;
    }
    __syncthreads();
    float mean = redA[0] * (1.0f / D_MODEL);
    float var  = redB[0] * (1.0f / D_MODEL) - mean * mean;
    float inv  = rsqrtf(var + LN_EPS);

    float4 g = ((const float4*)gamma)[tid];
    float4 b = ((const float4*)beta)[tid];
    float4 o;
    o.x = (v.x - mean) * inv * g.x + b.x;
    o.y = (v.y - mean) * inv * g.y + b.y;
    o.z = (v.z - mean) * inv * g.z + b.z;
    o.w = (v.w - mean) * inv * g.w + b.w;
    ((float4*)(y + (size_t)row * D_MODEL))[tid] = o;
}

// ---------------- GEMM (NT): Y = X @ W^T + bias -----------------------------
// 128x128 tile, BK=8, 256 threads, 8x8 micro-tile, double-buffered smem.
__device__ __forceinline__ void gemm128(const float* __restrict__ X,
                                        const float* __restrict__ W,
                                        const float* __restrict__ bias,
                                        float* __restrict__ Y)
{
    __shared__ float As[2][8][128 + 4];
    __shared__ float Bs[2][8][128 + 4];
    int tid = threadIdx.x;
    int bm = blockIdx.y, bn = blockIdx.x;
    int lr = tid >> 1;           // 0..127
    int lc = (tid & 1) * 4;      // 0 or 4
    const float* Xb = X + ((size_t)(bm * 128 + lr)) * D_MODEL + lc;
    const float* Wb = W + ((size_t)(bn * 128 + lr)) * D_MODEL + lc;
    int ty = tid >> 4, tx = tid & 15;

    float acc[8][8] = {};
    float4 xa = *(const float4*)Xb;
    float4 wa = *(const float4*)Wb;
    As[0][lc + 0][lr] = xa.x; As[0][lc + 1][lr] = xa.y;
    As[0][lc + 2][lr] = xa.z; As[0][lc + 3][lr] = xa.w;
    Bs[0][lc + 0][lr] = wa.x; Bs[0][lc + 1][lr] = wa.y;
    Bs[0][lc + 2][lr] = wa.z; Bs[0][lc + 3][lr] = wa.w;
    __syncthreads();

    const int NT = D_MODEL / 8;
    int p = 0;
    for (int kt = 0; kt < NT; kt++) {
        float4 xn, wn;
        if (kt + 1 < NT) {
            xn = *(const float4*)(Xb + (kt + 1) * 8);
            wn = *(const float4*)(Wb + (kt + 1) * 8);
        }
        #pragma unroll
        for (int k = 0; k < 8; k++) {
            float a[8], b[8];
            *(float4*)(a)     = *(const float4*)&As[p][k][ty * 8];
            *(float4*)(a + 4) = *(const float4*)&As[p][k][ty * 8 + 4];
            *(float4*)(b)     = *(const float4*)&Bs[p][k][tx * 8];
            *(float4*)(b + 4) = *(const float4*)&Bs[p][k][tx * 8 + 4];
            #pragma unroll
            for (int i = 0; i < 8; i++)
                #pragma unroll
                for (int j = 0; j < 8; j++)
                    acc[i][j] = fmaf(a[i], b[j], acc[i][j]);
        }
        if (kt + 1 < NT) {
            int q = 1 - p;
            As[q][lc + 0][lr] = xn.x; As[q][lc + 1][lr] = xn.y;
            As[q][lc + 2][lr] = xn.z; As[q][lc + 3][lr] = xn.w;
            Bs[q][lc + 0][lr] = wn.x; Bs[q][lc + 1][lr] = wn.y;
            Bs[q][lc + 2][lr] = wn.z; Bs[q][lc + 3][lr] = wn.w;
        }
        __syncthreads();
        p ^= 1;
    }

    int col0 = bn * 128 + tx * 8;
    float bv[8];
    #pragma unroll
    for (int j = 0; j < 8; j++) bv[j] = bias[col0 + j];
    #pragma unroll
    for (int i = 0; i < 8; i++) {
        int row = bm * 128 + ty * 8 + i;
        float* yr = Y + (size_t)row * D_MODEL + col0;
        float4 o0, o1;
        o0.x = acc[i][0] + bv[0]; o0.y = acc[i][1] + bv[1];
        o0.z = acc[i][2] + bv[2]; o0.w = acc[i][3] + bv[3];
        o1.x = acc[i][4] + bv[4]; o1.y = acc[i][5] + bv[5];
        o1.z = acc[i][6] + bv[6]; o1.w = acc[i][7] + bv[7];
        *(float4*)(yr)     = o0;
        *(float4*)(yr + 4) = o1;
    }
}

__global__ __launch_bounds__(256)
void qkv_proj_kernel(const float* __restrict__ Wq, const float* __restrict__ bq,
                     const float* __restrict__ Wk, const float* __restrict__ bk,
                     const float* __restrict__ Wv, const float* __restrict__ bv)
{
    int which = blockIdx.z;
    const float* X = (which == 0) ? g_qn : (which == 1) ? g_kn : g_vn;
    float* Y       = (which == 0) ? g_q  : (which == 1) ? g_k  : g_v;
    const float* W    = (which == 0) ? Wq : (which == 1) ? Wk : Wv;
    const float* bias = (which == 0) ? bq : (which == 1) ? bk : bv;
    gemm128(X, W, bias, Y);
}

__global__ __launch_bounds__(256)
void oproj_kernel(const float* __restrict__ W, const float* __restrict__ bias,
                  float* __restrict__ out)
{
    gemm128(g_ctx, W, bias, out);
}

// ---------------- scores: 128x128 tiles, causal-masked to 0 ----------------
__global__ __launch_bounds__(256)
void scores_kernel(float* __restrict__ attn_ext)
{
    float* attn = attn_ext ? attn_ext : g_attn_fb;
    int bh = blockIdx.z;
    int b = bh >> 4, h = bh & 15;
    int bt = blockIdx.y, bs = blockIdx.x;
    int tid = threadIdx.x;
    int ty = tid >> 4, tx = tid & 15;

    float* out = attn + ((size_t)bh * SEQ + bt * 128) * SEQ + bs * 128;

    if (bs > bt) {  // fully masked tile -> zeros
        float4 z = make_float4(0.f, 0.f, 0.f, 0.f);
        #pragma unroll
        for (int i = 0; i < 8; i++) {
            float* r = out + (size_t)(ty * 8 + i) * SEQ + tx * 8;
            *(float4*)(r) = z; *(float4*)(r + 4) = z;
        }
        return;
    }

    __shared__ float Qs[32][128 + 4];
    __shared__ float Ks[32][128 + 4];
    const float* Qb = g_q + ((size_t)(b * SEQ + bt * 128)) * D_MODEL + h * HEAD_DIM;
    const float* Kb = g_k + ((size_t)(b * SEQ + bs * 128)) * D_MODEL + h * HEAD_DIM;

    int lr = tid >> 1;           // 0..127
    int lcb = (tid & 1) * 4;     // 0 or 4
    float acc[8][8] = {};

    for (int kt = 0; kt < 2; kt++) {
        int k0 = kt * 32;
        #pragma unroll
        for (int pass = 0; pass < 4; pass++) {
            int c = lcb + pass * 8;
            float4 q4 = *(const float4*)(Qb + (size_t)lr * D_MODEL + k0 + c);
            float4 k4 = *(const float4*)(Kb + (size_t)lr * D_MODEL + k0 + c);
            Qs[c + 0][lr] = q4.x; Qs[c + 1][lr] = q4.y;
            Qs[c + 2][lr] = q4.z; Qs[c + 3][lr] = q4.w;
            Ks[c + 0][lr] = k4.x; Ks[c + 1][lr] = k4.y;
            Ks[c + 2][lr] = k4.z; Ks[c + 3][lr] = k4.w;
        }
        __syncthreads();
        #pragma unroll
        for (int k = 0; k < 32; k++) {
            float a[8], c[8];
            *(float4*)(a)     = *(const float4*)&Qs[k][ty * 8];
            *(float4*)(a + 4) = *(const float4*)&Qs[k][ty * 8 + 4];
            *(float4*)(c)     = *(const float4*)&Ks[k][tx * 8];
            *(float4*)(c + 4) = *(const float4*)&Ks[k][tx * 8 + 4];
            #pragma unroll
            for (int i = 0; i < 8; i++)
                #pragma unroll
                for (int j = 0; j < 8; j++)
                    acc[i][j] = fmaf(a[i], c[j], acc[i][j]);
        }
        __syncthreads();
    }

    const float scale = 0.125f;  // 64^-0.5
    #pragma unroll
    for (int i = 0; i < 8; i++) {
        int t = bt * 128 + ty * 8 + i;
        float* r = out + (size_t)(ty * 8 + i) * SEQ + tx * 8;
        float o[8];
        #pragma unroll
        for (int j = 0; j < 8; j++) {
            int s = bs * 128 + tx * 8 + j;
            o[j] = (s <= t) ? acc[i][j] * scale : 0.0f;
        }
        *(float4*)(r)     = *(float4*)(o);
        *(float4*)(r + 4) = *(float4*)(o + 4);
    }
}

// ---------------- causal softmax: one block per (b,h,t) row ---------------
__global__ void softmax_kernel(float* __restrict__ attn_ext)
{
    float* attn = attn_ext ? attn_ext : g_attn_fb;
    int row = blockIdx.x;
    int t = row & (SEQ - 1);
    int n = t + 1;
    float* p = attn + (size_t)row * SEQ;
    int tid = threadIdx.x;

    float vals[8];
    int cnt = 0;
    float m = -INFINITY;
    for (int i = tid; i < n; i += 256) {
        float x = p[i];
        vals[cnt++] = x;
        m = fmaxf(m, x);
    }
    __shared__ float redA[8], redB[8];
    #pragma unroll
    for (int o = 16; o > 0; o >>= 1) m = fmaxf(m, __shfl_xor_sync(0xffffffffu, m, o));
    int w = tid >> 5;
    if ((tid & 31) == 0) redA[w] = m;
    __syncthreads();
    if (tid == 0) {
        float mm = redA[0];
        #pragma unroll
        for (int i = 1; i < 8; i++) mm = fmaxf(mm, redA[i]);
        redA[0] = mm;
    }
    __syncthreads();
    m = redA[0];

    float s = 0.f;
    for (int j = 0; j < cnt; j++) { vals[j] = expf(vals[j] - m); s += vals[j]; }
    #pragma unroll
    for (int o = 16; o > 0; o >>= 1) s += __shfl_xor_sync(0xffffffffu, s, o);
    if ((tid & 31) == 0) redB[w] = s;
    __syncthreads();
    if (tid == 0) {
        float ss = 0.f;
        #pragma unroll
        for (int i = 0; i < 8; i++) ss += redB[i];
        redB[0] = ss;
    }
    __syncthreads();
    float inv = 1.0f / redB[0];

    cnt = 0;
    for (int i = tid; i < n; i += 256) p[i] = vals[cnt++] * inv;
}

// ---------------- AV: ctx = attn @ V ---------------------------------------
// 128(t) x 64(d) tile, BK=32, 256 threads, 4x8 micro-tile, reg prefetch.
__global__ __launch_bounds__(256)
void av_kernel(const float* __restrict__ attn_ext)
{
    const float* attn = attn_ext ? attn_ext : g_attn_fb;
    int bh = blockIdx.z;
    int b = bh >> 4, h = bh & 15;
    int bt = blockIdx.y;
    int tid = threadIdx.x;

    __shared__ float As[32][128 + 4];   // [s][t]
    __shared__ float Vs[32][64 + 4];    // [s][d]
    const float* Ab = attn + ((size_t)bh * SEQ + bt * 128) * SEQ;
    const float* Vb = g_v + (size_t)(b * SEQ) * D_MODEL + h * HEAD_DIM;

    int lr = tid >> 1;           // 0..127 (t row)
    int lcb = (tid & 1) * 4;
    int vs = tid >> 3;           // 0..31 (s row)
    int vd = (tid & 7) * 8;      // d col base
    int tyv = tid >> 3;          // 0..31 -> t rows tyv*4..+3
    int txv = tid & 7;           // 0..7  -> d cols txv*8..+7

    float acc[4][8] = {};
    const int NS = 4 * (bt + 1);

    // prefetch stage 0
    float4 pa[4], pv0, pv1;
    #pragma unroll
    for (int pass = 0; pass < 4; pass++)
        pa[pass] = *(const float4*)(Ab + (size_t)lr * SEQ + lcb + pass * 8);
    pv0 = *(const float4*)(Vb + (size_t)vs * D_MODEL + vd);
    pv1 = *(const float4*)(Vb + (size_t)vs * D_MODEL + vd + 4);

    for (int ks = 0; ks < NS; ks++) {
        #pragma unroll
        for (int pass = 0; pass < 4; pass++) {
            int c = lcb + pass * 8;
            As[c + 0][lr] = pa[pass].x; As[c + 1][lr] = pa[pass].y;
            As[c + 2][lr] = pa[pass].z; As[c + 3][lr] = pa[pass].w;
        }
        *(float4*)&Vs[vs][vd]     = pv0;
        *(float4*)&Vs[vs][vd + 4] = pv1;
        __syncthreads();

        if (ks + 1 < NS) {
            int s0 = (ks + 1) * 32;
            #pragma unroll
            for (int pass = 0; pass < 4; pass++)
                pa[pass] = *(const float4*)(Ab + (size_t)lr * SEQ + s0 + lcb + pass * 8);
            pv0 = *(const float4*)(Vb + (size_t)(s0 + vs) * D_MODEL + vd);
            pv1 = *(const float4*)(Vb + (size_t)(s0 + vs) * D_MODEL + vd + 4);
        }

        #pragma unroll
        for (int k = 0; k < 32; k++) {
            float a[4], c[8];
            *(float4*)(a)     = *(const float4*)&As[k][tyv * 4];
            *(float4*)(c)     = *(const float4*)&Vs[k][txv * 8];
            *(float4*)(c + 4) = *(const float4*)&Vs[k][txv * 8 + 4];
            #pragma unroll
            for (int i = 0; i < 4; i++)
                #pragma unroll
                for (int j = 0; j < 8; j++)
                    acc[i][j] = fmaf(a[i], c[j], acc[i][j]);
        }
        __syncthreads();
    }

    #pragma unroll
    for (int i = 0; i < 4; i++) {
        int row = b * SEQ + bt * 128 + tyv * 4 + i;
        float* yr = g_ctx + (size_t)row * D_MODEL + h * HEAD_DIM + txv * 8;
        *(float4*)(yr)     = *(float4*)&acc[i][0];
        *(float4*)(yr + 4) = *(float4*)&acc[i][4];
    }
}

// ---------------- launch ---------------------------------------------------
extern "C" void kernel_launch(void* const* d_in, const int* in_sizes, int n_in,
                              void* d_out, int out_size)
{
    const float* query = (const float*)d_in[0];
    const float* key_  = (const float*)d_in[1];
    const float* value = (const float*)d_in[2];
    const float* Wq = (const float*)d_in[3];
    const float* bq = (const float*)d_in[4];
    const float* Wk = (const float*)d_in[5];
    const float* bk = (const float*)d_in[6];
    const float* Wv = (const float*)d_in[7];
    const float* bv = (const float*)d_in[8];
    const float* Wo = (const float*)d_in[9];
    const float* bo = (const float*)d_in[10];
    const float* ln_g = (const float*)d_in[11];
    const float* ln_b = (const float*)d_in[12];

    float* out = (float*)d_out;
    float* attn = ((size_t)out_size >= OUT_ELEMS + ATTN_ELEMS)
                      ? out + OUT_ELEMS : nullptr;

    // 1. shared LayerNorm on q/k/v inputs (fused into one launch)
    ln_kernel<<<dim3(NTOK, 3), 256>>>(query, key_, value, ln_g, ln_b);

    // 2. Q/K/V projections (one launch, z = which)
    qkv_proj_kernel<<<dim3(D_MODEL / 128, NTOK / 128, 3), 256>>>(Wq, bq, Wk, bk, Wv, bv);

    // 3. scores (masked logits, zeros above diagonal)
    scores_kernel<<<dim3(SEQ / 128, SEQ / 128, BATCH * NHEAD), 256>>>(attn);

    // 4. causal softmax (in-place over valid region)
    softmax_kernel<<<BATCH * NHEAD * SEQ, 256>>>(attn);

    // 5. attn @ V -> ctx
    av_kernel<<<dim3(1, SEQ / 128, BATCH * NHEAD), 256>>>(attn);

    // 6. output projection
    oproj_kernel<<<dim3(D_MODEL / 128, NTOK / 128), 256>>>(Wo, bo, out);
}

// round 5
// speedup vs baseline: 2.1039x; 1.8881x over previous
#include <cuda_runtime.h>
#include <cuda_bf16.h>
#include <math.h>
#include <stdint.h>

#define D_MODEL 1024
#define NHEAD 16
#define HEAD_DIM 64
#define BATCH 2
#define SEQ 2048
#define NTOK (BATCH * SEQ)
#define OUT_ELEMS ((size_t)BATCH * SEQ * D_MODEL)
#define ATTN_ELEMS ((size_t)BATCH * NHEAD * SEQ * SEQ)
#define LN_EPS 1e-5f

// ---------------- scratch ---------------------------------------------------
__device__ float g_qn[NTOK * D_MODEL];
__device__ float g_kn[NTOK * D_MODEL];
__device__ float g_vn[NTOK * D_MODEL];
__device__ float g_q[NTOK * D_MODEL];
__device__ float g_k[NTOK * D_MODEL];
__device__ float g_v[NTOK * D_MODEL];
__device__ float g_vt[NTOK * D_MODEL];   // [bh][64 d][2048 s]
__device__ float g_ctx[NTOK * D_MODEL];
__device__ float g_attn_fb[ATTN_ELEMS];

// ---------------- helpers ----------------------------------------------------
__device__ __forceinline__ uint32_t smem_u32(const void* p) {
    uint32_t a;
    asm("{ .reg .u64 t; cvta.to.shared.u64 t, %1; cvt.u32.u64 %0, t; }"
        : "=r"(a) : "l"(p));
    return a;
}
__device__ __forceinline__ void ldm_x4(uint32_t* r, uint32_t addr) {
    asm volatile("ldmatrix.sync.aligned.m8n8.x4.shared.b16 {%0,%1,%2,%3}, [%4];"
                 : "=r"(r[0]), "=r"(r[1]), "=r"(r[2]), "=r"(r[3]) : "r"(addr));
}
__device__ __forceinline__ void mma_bf16(float* c, const uint32_t* a, const uint32_t* b) {
    asm volatile("mma.sync.aligned.m16n8k16.row.col.f32.bf16.bf16.f32 "
                 "{%0,%1,%2,%3}, {%4,%5,%6,%7}, {%8,%9}, {%0,%1,%2,%3};"
                 : "+f"(c[0]), "+f"(c[1]), "+f"(c[2]), "+f"(c[3])
                 : "r"(a[0]), "r"(a[1]), "r"(a[2]), "r"(a[3]), "r"(b[0]), "r"(b[1]));
}

// split fp32 float4 -> bf16 hi/lo; store 8B each into 80B-pitch smem rows
__device__ __forceinline__ void split_store80(char* hi, char* lo, int row, int col, float4 v) {
    int off = row * 80 + col * 2;
    __nv_bfloat162 h01 = __floats2bfloat162_rn(v.x, v.y);
    __nv_bfloat162 h23 = __floats2bfloat162_rn(v.z, v.w);
    float lx = v.x - __bfloat162float(h01.x);
    float ly = v.y - __bfloat162float(h01.y);
    float lz = v.z - __bfloat162float(h23.x);
    float lw = v.w - __bfloat162float(h23.y);
    __nv_bfloat162 l01 = __floats2bfloat162_rn(lx, ly);
    __nv_bfloat162 l23 = __floats2bfloat162_rn(lz, lw);
    uint2 hv, lv;
    hv.x = *(uint32_t*)&h01; hv.y = *(uint32_t*)&h23;
    lv.x = *(uint32_t*)&l01; lv.y = *(uint32_t*)&l23;
    *(uint2*)(hi + off) = hv;
    *(uint2*)(lo + off) = lv;
}

// ---------------- generic split-bf16 MMA core -------------------------------
// M tile = 128, N tile = BROWS, BK = 32 fp32, 256 threads (8 warps = WMN x WNN).
// acc[MF*NF][4] per warp; A,B read as [rows][K] fp32, K chunked by 32.
template<int BROWS, int WMN, int WNN>
__device__ __forceinline__ void gemm_core(const float* __restrict__ A, int lda,
                                          const float* __restrict__ B, int ldb,
                                          int NC, char* sm, float (*acc)[4])
{
    constexpr int MF = (128 / WMN) / 16;
    constexpr int NF = (BROWS / WNN) / 8;
    constexpr int ABYTES = 128 * 80;
    constexpr int BBYTES = BROWS * 80;
    constexpr int BUF = 2 * ABYTES + 2 * BBYTES;
    const int tid = threadIdx.x, wid = tid >> 5, lane = tid & 31;
    const int mr0 = (wid / WNN) * (128 / WMN);
    const int nr0 = (wid % WNN) * (BROWS / WNN);

    const int arow = tid >> 1, acb = (tid & 1) * 16;
    const float* Ap = A + (size_t)arow * lda + acb;
    constexpr int NB = (BROWS == 128) ? 4 : 2;
    int brow, bcb;
    if (BROWS == 128) { brow = tid >> 1; bcb = (tid & 1) * 16; }
    else              { brow = tid >> 2; bcb = (tid & 3) * 8; }
    const float* Bp = B + (size_t)brow * ldb + bcb;

    float4 ra[4], rb[NB];

    auto gload = [&](int c) {
        const float* pa = Ap + c * 32;
        ra[0] = *(const float4*)pa;       ra[1] = *(const float4*)(pa + 4);
        ra[2] = *(const float4*)(pa + 8); ra[3] = *(const float4*)(pa + 12);
        const float* pb = Bp + c * 32;
        rb[0] = *(const float4*)pb;       rb[1] = *(const float4*)(pb + 4);
        if (BROWS == 128) {
            rb[2] = *(const float4*)(pb + 8); rb[3] = *(const float4*)(pb + 12);
        }
    };
    auto sstore = [&](char* buf) {
        char* ahi = buf; char* alo = buf + ABYTES;
        split_store80(ahi, alo, arow, acb + 0,  ra[0]);
        split_store80(ahi, alo, arow, acb + 4,  ra[1]);
        split_store80(ahi, alo, arow, acb + 8,  ra[2]);
        split_store80(ahi, alo, arow, acb + 12, ra[3]);
        char* bhi = buf + 2 * ABYTES; char* blo = bhi + BBYTES;
        split_store80(bhi, blo, brow, bcb + 0, rb[0]);
        split_store80(bhi, blo, brow, bcb + 4, rb[1]);
        if (BROWS == 128) {
            split_store80(bhi, blo, brow, bcb + 8,  rb[2]);
            split_store80(bhi, blo, brow, bcb + 12, rb[3]);
        }
    };
    auto compute = [&](char* buf) {
        uint32_t ahi = smem_u32(buf);
        uint32_t bhi = ahi + 2 * ABYTES;
        const int ar  = mr0 + (lane & 15);
        const int bn_ = nr0 + ((lane >> 4) << 3) + (lane & 7);
        #pragma unroll
        for (int kk = 0; kk < 32; kk += 16) {
            const int akb = (kk + ((lane >> 4) << 3)) * 2;
            const int bkb = (kk + (((lane >> 3) & 1) << 3)) * 2;
            uint32_t Ah[MF][4], Al[MF][4], Bh[NF][2], Bl[NF][2];
            #pragma unroll
            for (int i = 0; i < MF; i++) {
                uint32_t ad = ahi + (uint32_t)(ar + i * 16) * 80 + akb;
                ldm_x4(Ah[i], ad);
                ldm_x4(Al[i], ad + ABYTES);
            }
            #pragma unroll
            for (int g = 0; g < NF / 2; g++) {
                uint32_t bd = bhi + (uint32_t)(bn_ + g * 16) * 80 + bkb;
                uint32_t t[4];
                ldm_x4(t, bd);
                Bh[2*g][0] = t[0]; Bh[2*g][1] = t[1];
                Bh[2*g+1][0] = t[2]; Bh[2*g+1][1] = t[3];
                ldm_x4(t, bd + BBYTES);
                Bl[2*g][0] = t[0]; Bl[2*g][1] = t[1];
                Bl[2*g+1][0] = t[2]; Bl[2*g+1][1] = t[3];
            }
            #pragma unroll
            for (int i = 0; i < MF; i++)
                #pragma unroll
                for (int j = 0; j < NF; j++) {
                    mma_bf16(acc[i*NF+j], Ah[i], Bh[j]);
                    mma_bf16(acc[i*NF+j], Ah[i], Bl[j]);
                    mma_bf16(acc[i*NF+j], Al[i], Bh[j]);
                }
        }
    };

    gload(0);
    sstore(sm);
    __syncthreads();
    int p = 0;
    for (int c = 0; c < NC; c++) {
        if (c + 1 < NC) gload(c + 1);
        compute(sm + p * BUF);
        if (c + 1 < NC) {
            sstore(sm + (1 - p) * BUF);
            __syncthreads();
            p ^= 1;
        }
    }
}

#define PJ_SMEM (2 * (2 * 128 * 80 + 2 * 128 * 80))   // 81920
#define AV_SMEM (2 * (2 * 128 * 80 + 2 * 64 * 80))    // 61440

// ---------------- LayerNorm -------------------------------------------------
__global__ void ln_kernel(const float* __restrict__ q_in,
                          const float* __restrict__ k_in,
                          const float* __restrict__ v_in,
                          const float* __restrict__ gamma,
                          const float* __restrict__ beta)
{
    int which = blockIdx.y;
    const float* x = (which == 0) ? q_in : (which == 1) ? k_in : v_in;
    float* __restrict__ y = (which == 0) ? g_qn : (which == 1) ? g_kn : g_vn;
    int row = blockIdx.x, tid = threadIdx.x;
    float4 v = ((const float4*)(x + (size_t)row * D_MODEL))[tid];
    float s  = v.x + v.y + v.z + v.w;
    float s2 = fmaf(v.x, v.x, fmaf(v.y, v.y, fmaf(v.z, v.z, v.w * v.w)));
    __shared__ float redA[8], redB[8];
    #pragma unroll
    for (int o = 16; o > 0; o >>= 1) {
        s  += __shfl_xor_sync(0xffffffffu, s, o);
        s2 += __shfl_xor_sync(0xffffffffu, s2, o);
    }
    int w = tid >> 5;
    if ((tid & 31) == 0) { redA[w] = s; redB[w] = s2; }
    __syncthreads();
    if (tid == 0) {
        float a = 0.f, b = 0.f;
        #pragma unroll
        for (int i = 0; i < 8; i++) { a += redA[i]; b += redB[i]; }
        redA[0] = a; redB[0] = b;
    }
    __syncthreads();
    float mean = redA[0] * (1.0f / D_MODEL);
    float var  = redB[0] * (1.0f / D_MODEL) - mean * mean;
    float inv  = rsqrtf(var + LN_EPS);
    float4 g = ((const float4*)gamma)[tid];
    float4 b = ((const float4*)beta)[tid];
    float4 o;
    o.x = (v.x - mean) * inv * g.x + b.x;
    o.y = (v.y - mean) * inv * g.y + b.y;
    o.z = (v.z - mean) * inv * g.z + b.z;
    o.w = (v.w - mean) * inv * g.w + b.w;
    ((float4*)(y + (size_t)row * D_MODEL))[tid] = o;
}

// ---------------- QKV / O projections ---------------------------------------
__global__ __launch_bounds__(256)
void qkv_mma_kernel(const float* __restrict__ Wq, const float* __restrict__ bq,
                    const float* __restrict__ Wk, const float* __restrict__ bk,
                    const float* __restrict__ Wv, const float* __restrict__ bv)
{
    extern __shared__ char sm[];
    int which = blockIdx.z;
    const float* X = (which == 0) ? g_qn : (which == 1) ? g_kn : g_vn;
    float* Y       = (which == 0) ? g_q  : (which == 1) ? g_k  : g_v;
    const float* W    = (which == 0) ? Wq : (which == 1) ? Wk : Wv;
    const float* bias = (which == 0) ? bq : (which == 1) ? bk : bv;
    int bm = blockIdx.y, bn = blockIdx.x;

    float acc[16][4];
    #pragma unroll
    for (int i = 0; i < 16; i++)
        acc[i][0] = acc[i][1] = acc[i][2] = acc[i][3] = 0.f;

    gemm_core<128, 2, 4>(X + (size_t)(bm * 128) * D_MODEL, D_MODEL,
                         W + (size_t)(bn * 128) * D_MODEL, D_MODEL,
                         32, sm, acc);

    int tid = threadIdx.x, wid = tid >> 5, lane = tid & 31;
    int mr0 = (wid >> 2) * 64, nr0 = (wid & 3) * 32;
    #pragma unroll
    for (int i = 0; i < 4; i++)
        #pragma unroll
        for (int j = 0; j < 4; j++) {
            int m = bm * 128 + mr0 + i * 16 + (lane >> 2);
            int n = bn * 128 + nr0 + j * 8 + (lane & 3) * 2;
            float b0 = bias[n], b1 = bias[n + 1];
            float* p = Y + (size_t)m * D_MODEL + n;
            float2 v0 = make_float2(acc[i*4+j][0] + b0, acc[i*4+j][1] + b1);
            float2 v1 = make_float2(acc[i*4+j][2] + b0, acc[i*4+j][3] + b1);
            *(float2*)p = v0;
            *(float2*)(p + 8 * D_MODEL) = v1;
        }
}

__global__ __launch_bounds__(256)
void oproj_mma_kernel(const float* __restrict__ W, const float* __restrict__ bias,
                      float* __restrict__ out)
{
    extern __shared__ char sm[];
    int bm = blockIdx.y, bn = blockIdx.x;
    float acc[16][4];
    #pragma unroll
    for (int i = 0; i < 16; i++)
        acc[i][0] = acc[i][1] = acc[i][2] = acc[i][3] = 0.f;

    gemm_core<128, 2, 4>(g_ctx + (size_t)(bm * 128) * D_MODEL, D_MODEL,
                         W + (size_t)(bn * 128) * D_MODEL, D_MODEL,
                         32, sm, acc);

    int tid = threadIdx.x, wid = tid >> 5, lane = tid & 31;
    int mr0 = (wid >> 2) * 64, nr0 = (wid & 3) * 32;
    #pragma unroll
    for (int i = 0; i < 4; i++)
        #pragma unroll
        for (int j = 0; j < 4; j++) {
            int m = bm * 128 + mr0 + i * 16 + (lane >> 2);
            int n = bn * 128 + nr0 + j * 8 + (lane & 3) * 2;
            float b0 = bias[n], b1 = bias[n + 1];
            float* p = out + (size_t)m * D_MODEL + n;
            *(float2*)p = make_float2(acc[i*4+j][0] + b0, acc[i*4+j][1] + b1);
            *(float2*)(p + 8 * D_MODEL) = make_float2(acc[i*4+j][2] + b0, acc[i*4+j][3] + b1);
        }
}

// ---------------- scores: masked scale * Q K^T -------------------------------
__global__ __launch_bounds__(256)
void scores_mma_kernel(float* __restrict__ attn_ext)
{
    float* attn = attn_ext ? attn_ext : g_attn_fb;
    int bh = blockIdx.z, bt = blockIdx.y, bs = blockIdx.x;
    int b = bh >> 4, h = bh & 15;
    int tid = threadIdx.x;
    float* outb = attn + ((size_t)bh * SEQ + bt * 128) * SEQ + bs * 128;

    if (bs > bt) {  // fully masked tile
        int row = tid >> 1, cb = (tid & 1) * 64;
        float4 z = make_float4(0.f, 0.f, 0.f, 0.f);
        float* r = outb + (size_t)row * SEQ + cb;
        #pragma unroll
        for (int j = 0; j < 64; j += 4) *(float4*)(r + j) = z;
        return;
    }

    extern __shared__ char sm[];
    float acc[16][4];
    #pragma unroll
    for (int i = 0; i < 16; i++)
        acc[i][0] = acc[i][1] = acc[i][2] = acc[i][3] = 0.f;

    const float* Qb = g_q + ((size_t)(b * SEQ + bt * 128)) * D_MODEL + h * HEAD_DIM;
    const float* Kb = g_k + ((size_t)(b * SEQ + bs * 128)) * D_MODEL + h * HEAD_DIM;
    gemm_core<128, 2, 4>(Qb, D_MODEL, Kb, D_MODEL, 2, sm, acc);

    int wid = tid >> 5, lane = tid & 31;
    int mr0 = (wid >> 2) * 64, nr0 = (wid & 3) * 32;
    const float scale = 0.125f;
    #pragma unroll
    for (int i = 0; i < 4; i++)
        #pragma unroll
        for (int j = 0; j < 4; j++) {
            int lt = mr0 + i * 16 + (lane >> 2);
            int ls = nr0 + j * 8 + (lane & 3) * 2;
            int tg0 = bt * 128 + lt, sg = bs * 128 + ls;
            float* p = outb + (size_t)lt * SEQ + ls;
            float2 v0, v1;
            v0.x = (sg     <= tg0) ? acc[i*4+j][0] * scale : 0.f;
            v0.y = (sg + 1 <= tg0) ? acc[i*4+j][1] * scale : 0.f;
            v1.x = (sg     <= tg0 + 8) ? acc[i*4+j][2] * scale : 0.f;
            v1.y = (sg + 1 <= tg0 + 8) ? acc[i*4+j][3] * scale : 0.f;
            *(float2*)p = v0;
            *(float2*)(p + 8 * SEQ) = v1;
        }
}

// ---------------- causal softmax --------------------------------------------
__global__ void softmax_kernel(float* __restrict__ attn_ext)
{
    float* attn = attn_ext ? attn_ext : g_attn_fb;
    int row = blockIdx.x;
    int t = row & (SEQ - 1);
    int n = t + 1;
    float* p = attn + (size_t)row * SEQ;
    int tid = threadIdx.x;
    float vals[8];
    int cnt = 0;
    float m = -INFINITY;
    for (int i = tid; i < n; i += 256) {
        float x = p[i];
        vals[cnt++] = x;
        m = fmaxf(m, x);
    }
    __shared__ float redA[8], redB[8];
    #pragma unroll
    for (int o = 16; o > 0; o >>= 1) m = fmaxf(m, __shfl_xor_sync(0xffffffffu, m, o));
    int w = tid >> 5;
    if ((tid & 31) == 0) redA[w] = m;
    __syncthreads();
    if (tid == 0) {
        float mm = redA[0];
        #pragma unroll
        for (int i = 1; i < 8; i++) mm = fmaxf(mm, redA[i]);
        redA[0] = mm;
    }
    __syncthreads();
    m = redA[0];
    float s = 0.f;
    for (int j = 0; j < cnt; j++) { vals[j] = expf(vals[j] - m); s += vals[j]; }
    #pragma unroll
    for (int o = 16; o > 0; o >>= 1) s += __shfl_xor_sync(0xffffffffu, s, o);
    if ((tid & 31) == 0) redB[w] = s;
    __syncthreads();
    if (tid == 0) {
        float ss = 0.f;
        #pragma unroll
        for (int i = 0; i < 8; i++) ss += redB[i];
        redB[0] = ss;
    }
    __syncthreads();
    float inv = 1.0f / redB[0];
    cnt = 0;
    for (int i = tid; i < n; i += 256) p[i] = vals[cnt++] * inv;
}

// ---------------- V transpose: g_vt[bh][d][s] --------------------------------
__global__ __launch_bounds__(256)
void vt_kernel()
{
    __shared__ float ts[64][65];
    int bh = blockIdx.y, s0 = blockIdx.x * 64;
    int b = bh >> 4, h = bh & 15;
    int tid = threadIdx.x;
    int d = tid & 63, sl0 = tid >> 6;
    #pragma unroll
    for (int p = 0; p < 16; p++) {
        int sl = p * 4 + sl0;
        ts[sl][d] = g_v[((size_t)(b * SEQ + s0 + sl)) * D_MODEL + h * 64 + d];
    }
    __syncthreads();
    int s = tid & 63, dl0 = tid >> 6;
    #pragma unroll
    for (int p = 0; p < 16; p++) {
        int dd = p * 4 + dl0;
        g_vt[((size_t)(bh * 64 + dd)) * SEQ + s0 + s] = ts[s][dd];
    }
}

// ---------------- AV: ctx = attn @ V -----------------------------------------
__global__ __launch_bounds__(256)
void av_mma_kernel(const float* __restrict__ attn_ext)
{
    const float* attn = attn_ext ? attn_ext : g_attn_fb;
    int bt = blockIdx.x, bh = blockIdx.y;
    int b = bh >> 4, h = bh & 15;
    int tid = threadIdx.x;

    extern __shared__ char sm[];
    float acc[8][4];
    #pragma unroll
    for (int i = 0; i < 8; i++)
        acc[i][0] = acc[i][1] = acc[i][2] = acc[i][3] = 0.f;

    const float* Ab = attn + ((size_t)bh * SEQ + bt * 128) * SEQ;
    const float* Vb = g_vt + ((size_t)bh * 64) * SEQ;
    int NC = 4 * (bt + 1);
    gemm_core<64, 4, 2>(Ab, SEQ, Vb, SEQ, NC, sm, acc);

    int wid = tid >> 5, lane = tid & 31;
    int mr0 = (wid >> 1) * 32, nr0 = (wid & 1) * 32;
    #pragma unroll
    for (int i = 0; i < 2; i++)
        #pragma unroll
        for (int j = 0; j < 4; j++) {
            int m = bt * 128 + mr0 + i * 16 + (lane >> 2);
            int n = h * 64 + nr0 + j * 8 + (lane & 3) * 2;
            float* p = g_ctx + ((size_t)(b * SEQ + m)) * D_MODEL + n;
            *(float2*)p = make_float2(acc[i*4+j][0], acc[i*4+j][1]);
            *(float2*)(p + 8 * D_MODEL) = make_float2(acc[i*4+j][2], acc[i*4+j][3]);
        }
}

// ---------------- launch ------------------------------------------------------
extern "C" void kernel_launch(void* const* d_in, const int* in_sizes, int n_in,
                              void* d_out, int out_size)
{
    const float* query = (const float*)d_in[0];
    const float* key_  = (const float*)d_in[1];
    const float* value = (const float*)d_in[2];
    const float* Wq = (const float*)d_in[3];
    const float* bq = (const float*)d_in[4];
    const float* Wk = (const float*)d_in[5];
    const float* bk = (const float*)d_in[6];
    const float* Wv = (const float*)d_in[7];
    const float* bv = (const float*)d_in[8];
    const float* Wo = (const float*)d_in[9];
    const float* bo = (const float*)d_in[10];
    const float* ln_g = (const float*)d_in[11];
    const float* ln_b = (const float*)d_in[12];

    float* out = (float*)d_out;
    float* attn = ((size_t)out_size >= OUT_ELEMS + ATTN_ELEMS)
                      ? out + OUT_ELEMS : nullptr;

    static int attr_done = 0;
    if (!attr_done) {
        cudaFuncSetAttribute(qkv_mma_kernel,    cudaFuncAttributeMaxDynamicSharedMemorySize, PJ_SMEM);
        cudaFuncSetAttribute(oproj_mma_kernel,  cudaFuncAttributeMaxDynamicSharedMemorySize, PJ_SMEM);
        cudaFuncSetAttribute(scores_mma_kernel, cudaFuncAttributeMaxDynamicSharedMemorySize, PJ_SMEM);
        cudaFuncSetAttribute(av_mma_kernel,     cudaFuncAttributeMaxDynamicSharedMemorySize, AV_SMEM);
        attr_done = 1;
    }

    ln_kernel<<<dim3(NTOK, 3), 256>>>(query, key_, value, ln_g, ln_b);

    qkv_mma_kernel<<<dim3(D_MODEL / 128, NTOK / 128, 3), 256, PJ_SMEM>>>(
        Wq, bq, Wk, bk, Wv, bv);

    scores_mma_kernel<<<dim3(SEQ / 128, SEQ / 128, BATCH * NHEAD), 256, PJ_SMEM>>>(attn);

    softmax_kernel<<<BATCH * NHEAD * SEQ, 256>>>(attn);

    vt_kernel<<<dim3(SEQ / 64, BATCH * NHEAD), 256>>>();

    av_mma_kernel<<<dim3(SEQ / 128, BATCH * NHEAD), 256, AV_SMEM>>>(attn);

    oproj_mma_kernel<<<dim3(D_MODEL / 128, NTOK / 128), 256, PJ_SMEM>>>(Wo, bo, out);
}

// round 7
// speedup vs baseline: 2.2573x; 1.0729x over previous
#include <cuda_runtime.h>
#include <cuda_bf16.h>
#include <math.h>
#include <stdint.h>

#define D_MODEL 1024
#define NHEAD 16
#define HEAD_DIM 64
#define BATCH 2
#define SEQ 2048
#define NTOK (BATCH * SEQ)
#define OUT_ELEMS ((size_t)BATCH * SEQ * D_MODEL)
#define ATTN_ELEMS ((size_t)BATCH * NHEAD * SEQ * SEQ)
#define LN_EPS 1e-5f
#define NEG_BIG -3e38f

// ---------------- scratch ---------------------------------------------------
__device__ float g_qn[NTOK * D_MODEL];
__device__ float g_kn[NTOK * D_MODEL];
__device__ float g_vn[NTOK * D_MODEL];
__device__ float g_q[NTOK * D_MODEL];
__device__ float g_k[NTOK * D_MODEL];
__device__ float g_v[NTOK * D_MODEL];
__device__ float g_vt[NTOK * D_MODEL];   // [bh][64 d][2048 s]
__device__ float g_ctx[NTOK * D_MODEL];
__device__ float g_attn_fb[ATTN_ELEMS];

// ---------------- helpers ----------------------------------------------------
__device__ __forceinline__ uint32_t smem_u32(const void* p) {
    uint32_t a;
    asm("{ .reg .u64 t; cvta.to.shared.u64 t, %1; cvt.u32.u64 %0, t; }"
        : "=r"(a) : "l"(p));
    return a;
}
__device__ __forceinline__ void ldm_x4(uint32_t* r, uint32_t addr) {
    asm volatile("ldmatrix.sync.aligned.m8n8.x4.shared.b16 {%0,%1,%2,%3}, [%4];"
                 : "=r"(r[0]), "=r"(r[1]), "=r"(r[2]), "=r"(r[3]) : "r"(addr));
}
__device__ __forceinline__ void mma_bf16(float* c, const uint32_t* a, const uint32_t* b) {
    asm volatile("mma.sync.aligned.m16n8k16.row.col.f32.bf16.bf16.f32 "
                 "{%0,%1,%2,%3}, {%4,%5,%6,%7}, {%8,%9}, {%0,%1,%2,%3};"
                 : "+f"(c[0]), "+f"(c[1]), "+f"(c[2]), "+f"(c[3])
                 : "r"(a[0]), "r"(a[1]), "r"(a[2]), "r"(a[3]), "r"(b[0]), "r"(b[1]));
}

// split fp32 float4 -> bf16 hi/lo; store 8B each into PITCH-byte rows
template<int PITCH>
__device__ __forceinline__ void split_storeP(char* hi, char* lo, int row, int col, float4 v) {
    int off = row * PITCH + col * 2;
    __nv_bfloat162 h01 = __floats2bfloat162_rn(v.x, v.y);
    __nv_bfloat162 h23 = __floats2bfloat162_rn(v.z, v.w);
    float lx = v.x - __bfloat162float(h01.x);
    float ly = v.y - __bfloat162float(h01.y);
    float lz = v.z - __bfloat162float(h23.x);
    float lw = v.w - __bfloat162float(h23.y);
    __nv_bfloat162 l01 = __floats2bfloat162_rn(lx, ly);
    __nv_bfloat162 l23 = __floats2bfloat162_rn(lz, lw);
    uint2 hv, lv;
    hv.x = *(uint32_t*)&h01; hv.y = *(uint32_t*)&h23;
    lv.x = *(uint32_t*)&l01; lv.y = *(uint32_t*)&l23;
    *(uint2*)(hi + off) = hv;
    *(uint2*)(lo + off) = lv;
}

// ---------------- generic split-bf16 MMA core (projections) -----------------
template<int BROWS, int WMN, int WNN>
__device__ __forceinline__ void gemm_core(const float* __restrict__ A, int lda,
                                          const float* __restrict__ B, int ldb,
                                          int NC, char* sm, float (*acc)[4])
{
    constexpr int MF = (128 / WMN) / 16;
    constexpr int NF = (BROWS / WNN) / 8;
    constexpr int ABYTES = 128 * 80;
    constexpr int BBYTES = BROWS * 80;
    constexpr int BUF = 2 * ABYTES + 2 * BBYTES;
    const int tid = threadIdx.x, wid = tid >> 5, lane = tid & 31;
    const int mr0 = (wid / WNN) * (128 / WMN);
    const int nr0 = (wid % WNN) * (BROWS / WNN);

    const int arow = tid >> 1, acb = (tid & 1) * 16;
    const float* Ap = A + (size_t)arow * lda + acb;
    int brow = tid >> 1, bcb = (tid & 1) * 16;
    const float* Bp = B + (size_t)brow * ldb + bcb;

    float4 ra[4], rb[4];
    auto gload = [&](int c) {
        const float* pa = Ap + c * 32;
        ra[0] = *(const float4*)pa;       ra[1] = *(const float4*)(pa + 4);
        ra[2] = *(const float4*)(pa + 8); ra[3] = *(const float4*)(pa + 12);
        const float* pb = Bp + c * 32;
        rb[0] = *(const float4*)pb;       rb[1] = *(const float4*)(pb + 4);
        rb[2] = *(const float4*)(pb + 8); rb[3] = *(const float4*)(pb + 12);
    };
    auto sstore = [&](char* buf) {
        char* ahi = buf; char* alo = buf + ABYTES;
        split_storeP<80>(ahi, alo, arow, acb + 0,  ra[0]);
        split_storeP<80>(ahi, alo, arow, acb + 4,  ra[1]);
        split_storeP<80>(ahi, alo, arow, acb + 8,  ra[2]);
        split_storeP<80>(ahi, alo, arow, acb + 12, ra[3]);
        char* bhi = buf + 2 * ABYTES; char* blo = bhi + BBYTES;
        split_storeP<80>(bhi, blo, brow, bcb + 0, rb[0]);
        split_storeP<80>(bhi, blo, brow, bcb + 4, rb[1]);
        split_storeP<80>(bhi, blo, brow, bcb + 8,  rb[2]);
        split_storeP<80>(bhi, blo, brow, bcb + 12, rb[3]);
    };
    auto compute = [&](char* buf) {
        uint32_t ahi = smem_u32(buf);
        uint32_t bhi = ahi + 2 * ABYTES;
        const int ar  = mr0 + (lane & 15);
        const int bn_ = nr0 + ((lane >> 4) << 3) + (lane & 7);
        #pragma unroll
        for (int kk = 0; kk < 32; kk += 16) {
            const int akb = (kk + ((lane >> 4) << 3)) * 2;
            const int bkb = (kk + (((lane >> 3) & 1) << 3)) * 2;
            uint32_t Ah[MF][4], Al[MF][4], Bh[NF][2], Bl[NF][2];
            #pragma unroll
            for (int i = 0; i < MF; i++) {
                uint32_t ad = ahi + (uint32_t)(ar + i * 16) * 80 + akb;
                ldm_x4(Ah[i], ad);
                ldm_x4(Al[i], ad + ABYTES);
            }
            #pragma unroll
            for (int g = 0; g < NF / 2; g++) {
                uint32_t bd = bhi + (uint32_t)(bn_ + g * 16) * 80 + bkb;
                uint32_t t[4];
                ldm_x4(t, bd);
                Bh[2*g][0] = t[0]; Bh[2*g][1] = t[1];
                Bh[2*g+1][0] = t[2]; Bh[2*g+1][1] = t[3];
                ldm_x4(t, bd + BBYTES);
                Bl[2*g][0] = t[0]; Bl[2*g][1] = t[1];
                Bl[2*g+1][0] = t[2]; Bl[2*g+1][1] = t[3];
            }
            #pragma unroll
            for (int i = 0; i < MF; i++)
                #pragma unroll
                for (int j = 0; j < NF; j++) {
                    mma_bf16(acc[i*NF+j], Ah[i], Bh[j]);
                    mma_bf16(acc[i*NF+j], Ah[i], Bl[j]);
                    mma_bf16(acc[i*NF+j], Al[i], Bh[j]);
                }
        }
    };

    gload(0);
    sstore(sm);
    __syncthreads();
    int p = 0;
    for (int c = 0; c < NC; c++) {
        if (c + 1 < NC) gload(c + 1);
        compute(sm + p * BUF);
        if (c + 1 < NC) {
            sstore(sm + (1 - p) * BUF);
            __syncthreads();
            p ^= 1;
        }
    }
}

#define PJ_SMEM (2 * (2 * 128 * 80 + 2 * 128 * 80))   // 81920

// ---------------- LayerNorm -------------------------------------------------
__global__ void ln_kernel(const float* __restrict__ q_in,
                          const float* __restrict__ k_in,
                          const float* __restrict__ v_in,
                          const float* __restrict__ gamma,
                          const float* __restrict__ beta)
{
    int which = blockIdx.y;
    const float* x = (which == 0) ? q_in : (which == 1) ? k_in : v_in;
    float* __restrict__ y = (which == 0) ? g_qn : (which == 1) ? g_kn : g_vn;
    int row = blockIdx.x, tid = threadIdx.x;
    float4 v = ((const float4*)(x + (size_t)row * D_MODEL))[tid];
    float s  = v.x + v.y + v.z + v.w;
    float s2 = fmaf(v.x, v.x, fmaf(v.y, v.y, fmaf(v.z, v.z, v.w * v.w)));
    __shared__ float redA[8], redB[8];
    #pragma unroll
    for (int o = 16; o > 0; o >>= 1) {
        s  += __shfl_xor_sync(0xffffffffu, s, o);
        s2 += __shfl_xor_sync(0xffffffffu, s2, o);
    }
    int w = tid >> 5;
    if ((tid & 31) == 0) { redA[w] = s; redB[w] = s2; }
    __syncthreads();
    if (tid == 0) {
        float a = 0.f, b = 0.f;
        #pragma unroll
        for (int i = 0; i < 8; i++) { a += redA[i]; b += redB[i]; }
        redA[0] = a; redB[0] = b;
    }
    __syncthreads();
    float mean = redA[0] * (1.0f / D_MODEL);
    float var  = redB[0] * (1.0f / D_MODEL) - mean * mean;
    float inv  = rsqrtf(var + LN_EPS);
    float4 g = ((const float4*)gamma)[tid];
    float4 b = ((const float4*)beta)[tid];
    float4 o;
    o.x = (v.x - mean) * inv * g.x + b.x;
    o.y = (v.y - mean) * inv * g.y + b.y;
    o.z = (v.z - mean) * inv * g.z + b.z;
    o.w = (v.w - mean) * inv * g.w + b.w;
    ((float4*)(y + (size_t)row * D_MODEL))[tid] = o;
}

// ---------------- QKV / O projections ---------------------------------------
__global__ __launch_bounds__(256)
void qkv_mma_kernel(const float* __restrict__ Wq, const float* __restrict__ bq,
                    const float* __restrict__ Wk, const float* __restrict__ bk,
                    const float* __restrict__ Wv, const float* __restrict__ bv)
{
    extern __shared__ char sm[];
    int which = blockIdx.z;
    const float* X = (which == 0) ? g_qn : (which == 1) ? g_kn : g_vn;
    float* Y       = (which == 0) ? g_q  : (which == 1) ? g_k  : g_v;
    const float* W    = (which == 0) ? Wq : (which == 1) ? Wk : Wv;
    const float* bias = (which == 0) ? bq : (which == 1) ? bk : bv;
    int bm = blockIdx.y, bn = blockIdx.x;

    float acc[16][4];
    #pragma unroll
    for (int i = 0; i < 16; i++)
        acc[i][0] = acc[i][1] = acc[i][2] = acc[i][3] = 0.f;

    gemm_core<128, 2, 4>(X + (size_t)(bm * 128) * D_MODEL, D_MODEL,
                         W + (size_t)(bn * 128) * D_MODEL, D_MODEL,
                         32, sm, acc);

    int tid = threadIdx.x, wid = tid >> 5, lane = tid & 31;
    int mr0 = (wid >> 2) * 64, nr0 = (wid & 3) * 32;
    #pragma unroll
    for (int i = 0; i < 4; i++)
        #pragma unroll
        for (int j = 0; j < 4; j++) {
            int m = bm * 128 + mr0 + i * 16 + (lane >> 2);
            int n = bn * 128 + nr0 + j * 8 + (lane & 3) * 2;
            float b0 = bias[n], b1 = bias[n + 1];
            float* p = Y + (size_t)m * D_MODEL + n;
            *(float2*)p = make_float2(acc[i*4+j][0] + b0, acc[i*4+j][1] + b1);
            *(float2*)(p + 8 * D_MODEL) = make_float2(acc[i*4+j][2] + b0, acc[i*4+j][3] + b1);
        }
}

__global__ __launch_bounds__(256)
void oproj_mma_kernel(const float* __restrict__ W, const float* __restrict__ bias,
                      float* __restrict__ out)
{
    extern __shared__ char sm[];
    int bm = blockIdx.y, bn = blockIdx.x;
    float acc[16][4];
    #pragma unroll
    for (int i = 0; i < 16; i++)
        acc[i][0] = acc[i][1] = acc[i][2] = acc[i][3] = 0.f;

    gemm_core<128, 2, 4>(g_ctx + (size_t)(bm * 128) * D_MODEL, D_MODEL,
                         W + (size_t)(bn * 128) * D_MODEL, D_MODEL,
                         32, sm, acc);

    int tid = threadIdx.x, wid = tid >> 5, lane = tid & 31;
    int mr0 = (wid >> 2) * 64, nr0 = (wid & 3) * 32;
    #pragma unroll
    for (int i = 0; i < 4; i++)
        #pragma unroll
        for (int j = 0; j < 4; j++) {
            int m = bm * 128 + mr0 + i * 16 + (lane >> 2);
            int n = bn * 128 + nr0 + j * 8 + (lane & 3) * 2;
            float b0 = bias[n], b1 = bias[n + 1];
            float* p = out + (size_t)m * D_MODEL + n;
            *(float2*)p = make_float2(acc[i*4+j][0] + b0, acc[i*4+j][1] + b1);
            *(float2*)(p + 8 * D_MODEL) = make_float2(acc[i*4+j][2] + b0, acc[i*4+j][3] + b1);
        }
}

// ---------------- V transpose: g_vt[bh][d][s] --------------------------------
__global__ __launch_bounds__(256)
void vt_kernel()
{
    __shared__ float ts[64][65];
    int bh = blockIdx.y, s0 = blockIdx.x * 64;
    int b = bh >> 4, h = bh & 15;
    int tid = threadIdx.x;
    int d = tid & 63, sl0 = tid >> 6;
    #pragma unroll
    for (int p = 0; p < 16; p++) {
        int sl = p * 4 + sl0;
        ts[sl][d] = g_v[((size_t)(b * SEQ + s0 + sl)) * D_MODEL + h * 64 + d];
    }
    __syncthreads();
    int s = tid & 63, dl0 = tid >> 6;
    #pragma unroll
    for (int p = 0; p < 16; p++) {
        int dd = p * 4 + dl0;
        g_vt[((size_t)(bh * 64 + dd)) * SEQ + s0 + s] = ts[s][dd];
    }
}

// ---------------- zero-fill of masked upper tiles ----------------------------
__global__ __launch_bounds__(256)
void zerofill_kernel(float* __restrict__ attn)
{
    int bs = blockIdx.x, bt = blockIdx.y, bh = blockIdx.z;
    if (bs <= bt) return;
    float* o = attn + ((size_t)bh * SEQ + bt * 128) * SEQ + bs * 128;
    int tid = threadIdx.x;
    float4 z = make_float4(0.f, 0.f, 0.f, 0.f);
    #pragma unroll
    for (int r8 = 0; r8 < 16; r8++) {
        int row = r8 * 8 + (tid >> 5);
        *(float4*)(o + (size_t)row * SEQ + (tid & 31) * 4) = z;
    }
}

// ---------------- fused scores + softmax + AV --------------------------------
// smem layout (bytes):
#define FA_QHI 0
#define FA_QLO 18432
#define FA_KHI 36864
#define FA_KLO 55296
#define FA_VHI 73728
#define FA_VLO 91136
#define FA_PHI 108544
#define FA_PLO 143360
#define FA_WST 178176
#define FA_RST 182272
#define FA_SMEM 183296

// S-tile MMA: acc += Q(128x64) @ K^T(128x64), both split hi/lo in smem (pitch 144)
__device__ __forceinline__ void mma_tile_S(uint32_t sb, float (*acc)[4],
                                           int mr0, int nr0, int lane)
{
    uint32_t qhi = sb + FA_QHI, khi = sb + FA_KHI;
    const int ar  = mr0 + (lane & 15);
    const int bn_ = nr0 + ((lane >> 4) << 3) + (lane & 7);
    #pragma unroll
    for (int kk = 0; kk < 64; kk += 16) {
        const int akb = (kk + ((lane >> 4) << 3)) * 2;
        const int bkb = (kk + (((lane >> 3) & 1) << 3)) * 2;
        uint32_t Ah[4][4], Al[4][4], Bh[4][2], Bl[4][2];
        #pragma unroll
        for (int i = 0; i < 4; i++) {
            uint32_t ad = qhi + (uint32_t)(ar + i * 16) * 144 + akb;
            ldm_x4(Ah[i], ad);
            ldm_x4(Al[i], ad + (FA_QLO - FA_QHI));
        }
        #pragma unroll
        for (int g = 0; g < 2; g++) {
            uint32_t bd = khi + (uint32_t)(bn_ + g * 16) * 144 + bkb;
            uint32_t t[4];
            ldm_x4(t, bd);
            Bh[2*g][0] = t[0]; Bh[2*g][1] = t[1];
            Bh[2*g+1][0] = t[2]; Bh[2*g+1][1] = t[3];
            ldm_x4(t, bd + (FA_KLO - FA_KHI));
            Bl[2*g][0] = t[0]; Bl[2*g][1] = t[1];
            Bl[2*g+1][0] = t[2]; Bl[2*g+1][1] = t[3];
        }
        #pragma unroll
        for (int i = 0; i < 4; i++)
            #pragma unroll
            for (int j = 0; j < 4; j++) {
                mma_bf16(acc[i*4+j], Ah[i], Bh[j]);
                mma_bf16(acc[i*4+j], Ah[i], Bl[j]);
                mma_bf16(acc[i*4+j], Al[i], Bh[j]);
            }
    }
}

__global__ __launch_bounds__(256, 1)
void fused_attn_kernel(float* __restrict__ attn)
{
    extern __shared__ char sm[];
    uint32_t sb = smem_u32(sm);
    const int bt = 15 - blockIdx.x;          // longest first
    const int bh = blockIdx.y;
    const int b = bh >> 4, h = bh & 15;
    const int tid = threadIdx.x, wid = tid >> 5, lane = tid & 31;
    const int mr0 = (wid >> 2) * 64;         // warp row half
    const int wq = wid & 3;                  // warp col quarter
    const int nr0 = wq * 32;
    const float SC = 0.125f * 1.4426950408889634f;  // scale * log2(e)

    float2* wst = (float2*)(sm + FA_WST);    // [4 warpcols][128 rows]
    float2* rst = (float2*)(sm + FA_RST);    // [128 rows] (M, invZ)

    // ---- load Q tile (persistent) ----
    {
        const float* Qb = g_q + ((size_t)(b * SEQ + bt * 128)) * D_MODEL + h * 64;
        int row = tid >> 1, cb = (tid & 1) * 32;
        const float* p = Qb + (size_t)row * D_MODEL + cb;
        #pragma unroll
        for (int q = 0; q < 8; q++)
            split_storeP<144>(sm + FA_QHI, sm + FA_QLO, row, cb + q * 4,
                              *(const float4*)(p + q * 4));
    }

    float mrun[8], zrun[8];
    #pragma unroll
    for (int s = 0; s < 8; s++) { mrun[s] = NEG_BIG; zrun[s] = 0.f; }

    const int NT = bt + 1;

    // ================= phase 1: stats =================
    for (int bs = 0; bs < NT; bs++) {
        {   // load K tile
            const float* Kb = g_k + ((size_t)(b * SEQ + bs * 128)) * D_MODEL + h * 64;
            int row = tid >> 1, cb = (tid & 1) * 32;
            const float* p = Kb + (size_t)row * D_MODEL + cb;
            #pragma unroll
            for (int q = 0; q < 8; q++)
                split_storeP<144>(sm + FA_KHI, sm + FA_KLO, row, cb + q * 4,
                                  *(const float4*)(p + q * 4));
        }
        __syncthreads();
        float acc[16][4];
        #pragma unroll
        for (int i = 0; i < 16; i++)
            acc[i][0] = acc[i][1] = acc[i][2] = acc[i][3] = 0.f;
        mma_tile_S(sb, acc, mr0, nr0, lane);

        bool diag = (bs == bt);
        #pragma unroll
        for (int i = 0; i < 4; i++) {
            float av[4][4];
            float tm0 = NEG_BIG, tm1 = NEG_BIG;
            int ltA = mr0 + i * 16 + (lane >> 2);
            int tg0 = bt * 128 + ltA, tg1 = tg0 + 8;
            #pragma unroll
            for (int j = 0; j < 4; j++) {
                int sg = bs * 128 + nr0 + j * 8 + ((lane & 3) << 1);
                float* A = acc[i*4+j];
                av[j][0] = (diag && sg     > tg0) ? NEG_BIG : A[0] * SC;
                av[j][1] = (diag && sg + 1 > tg0) ? NEG_BIG : A[1] * SC;
                av[j][2] = (diag && sg     > tg1) ? NEG_BIG : A[2] * SC;
                av[j][3] = (diag && sg + 1 > tg1) ? NEG_BIG : A[3] * SC;
                tm0 = fmaxf(tm0, fmaxf(av[j][0], av[j][1]));
                tm1 = fmaxf(tm1, fmaxf(av[j][2], av[j][3]));
            }
            {
                int s = i * 2;
                float mn = fmaxf(mrun[s], tm0);
                float zs = zrun[s] * exp2f(mrun[s] - mn);
                #pragma unroll
                for (int j = 0; j < 4; j++) {
                    zs += (av[j][0] > -1e38f) ? exp2f(av[j][0] - mn) : 0.f;
                    zs += (av[j][1] > -1e38f) ? exp2f(av[j][1] - mn) : 0.f;
                }
                mrun[s] = mn; zrun[s] = zs;
            }
            {
                int s = i * 2 + 1;
                float mn = fmaxf(mrun[s], tm1);
                float zs = zrun[s] * exp2f(mrun[s] - mn);
                #pragma unroll
                for (int j = 0; j < 4; j++) {
                    zs += (av[j][2] > -1e38f) ? exp2f(av[j][2] - mn) : 0.f;
                    zs += (av[j][3] > -1e38f) ? exp2f(av[j][3] - mn) : 0.f;
                }
                mrun[s] = mn; zrun[s] = zs;
            }
        }
        __syncthreads();
    }

    // ---- merge stats across lane&3 (cols within warp) ----
    #pragma unroll
    for (int s = 0; s < 8; s++) {
        float m = mrun[s], z = zrun[s];
        #pragma unroll
        for (int off = 1; off <= 2; off <<= 1) {
            float om = __shfl_xor_sync(0xffffffffu, m, off);
            float oz = __shfl_xor_sync(0xffffffffu, z, off);
            float mn = fmaxf(m, om);
            z = z * exp2f(m - mn) + oz * exp2f(om - mn);
            m = mn;
        }
        mrun[s] = m; zrun[s] = z;
    }
    if ((lane & 3) == 0) {
        #pragma unroll
        for (int s = 0; s < 8; s++) {
            int row = mr0 + (s >> 1) * 16 + (s & 1) * 8 + (lane >> 2);
            wst[wq * 128 + row] = make_float2(mrun[s], zrun[s]);
        }
    }
    __syncthreads();
    if (tid < 128) {
        float M = NEG_BIG, Z = 0.f;
        #pragma unroll
        for (int wc = 0; wc < 4; wc++) {
            float2 v = wst[wc * 128 + tid];
            float mn = fmaxf(M, v.x);
            Z = Z * exp2f(M - mn) + v.y * exp2f(v.x - mn);
            M = mn;
        }
        rst[tid] = make_float2(M, 1.f / Z);
    }
    __syncthreads();

    float Mr[8], IZ[8];
    #pragma unroll
    for (int s = 0; s < 8; s++) {
        int row = mr0 + (s >> 1) * 16 + (s & 1) * 8 + (lane >> 2);
        float2 v = rst[row];
        Mr[s] = v.x; IZ[s] = v.y;
    }
    __syncthreads();

    // ================= phase 2: recompute, normalize, write attn, P@V =======
    float cacc[8][4];
    #pragma unroll
    for (int i = 0; i < 8; i++)
        cacc[i][0] = cacc[i][1] = cacc[i][2] = cacc[i][3] = 0.f;

    float* outb0 = attn + ((size_t)bh * SEQ + bt * 128) * SEQ;

    for (int bs = 0; bs < NT; bs++) {
        {   // load K tile
            const float* Kb = g_k + ((size_t)(b * SEQ + bs * 128)) * D_MODEL + h * 64;
            int row = tid >> 1, cb = (tid & 1) * 32;
            const float* p = Kb + (size_t)row * D_MODEL + cb;
            #pragma unroll
            for (int q = 0; q < 8; q++)
                split_storeP<144>(sm + FA_KHI, sm + FA_KLO, row, cb + q * 4,
                                  *(const float4*)(p + q * 4));
        }
        {   // load V tile (Vt rows d=64, cols s; pitch 272)
            const float* Vb = g_vt + ((size_t)(bh * 64)) * SEQ + bs * 128;
            int row = tid >> 2, cb = (tid & 3) * 32;
            const float* p = Vb + (size_t)row * SEQ + cb;
            #pragma unroll
            for (int q = 0; q < 8; q++)
                split_storeP<272>(sm + FA_VHI, sm + FA_VLO, row, cb + q * 4,
                                  *(const float4*)(p + q * 4));
        }
        __syncthreads();

        float acc[16][4];
        #pragma unroll
        for (int i = 0; i < 16; i++)
            acc[i][0] = acc[i][1] = acc[i][2] = acc[i][3] = 0.f;
        mma_tile_S(sb, acc, mr0, nr0, lane);

        bool diag = (bs == bt);
        float* outb = outb0 + bs * 128;
        #pragma unroll
        for (int i = 0; i < 4; i++) {
            int ltA = mr0 + i * 16 + (lane >> 2);
            int tg0 = bt * 128 + ltA, tg1 = tg0 + 8;
            #pragma unroll
            for (int j = 0; j < 4; j++) {
                int lsl = nr0 + j * 8 + ((lane & 3) << 1);
                int sg = bs * 128 + lsl;
                float* A = acc[i*4+j];
                float p0 = exp2f(A[0] * SC - Mr[i*2])   * IZ[i*2];
                float p1 = exp2f(A[1] * SC - Mr[i*2])   * IZ[i*2];
                float p2 = exp2f(A[2] * SC - Mr[i*2+1]) * IZ[i*2+1];
                float p3 = exp2f(A[3] * SC - Mr[i*2+1]) * IZ[i*2+1];
                if (diag) {
                    if (sg     > tg0) p0 = 0.f;
                    if (sg + 1 > tg0) p1 = 0.f;
                    if (sg     > tg1) p2 = 0.f;
                    if (sg + 1 > tg1) p3 = 0.f;
                }
                *(float2*)(outb + (size_t)ltA * SEQ + lsl) = make_float2(p0, p1);
                *(float2*)(outb + (size_t)(ltA + 8) * SEQ + lsl) = make_float2(p2, p3);
                __nv_bfloat162 h01 = __floats2bfloat162_rn(p0, p1);
                __nv_bfloat162 l01 = __floats2bfloat162_rn(
                    p0 - __bfloat162float(h01.x), p1 - __bfloat162float(h01.y));
                __nv_bfloat162 h23 = __floats2bfloat162_rn(p2, p3);
                __nv_bfloat162 l23 = __floats2bfloat162_rn(
                    p2 - __bfloat162float(h23.x), p3 - __bfloat162float(h23.y));
                *(uint32_t*)(sm + FA_PHI + ltA * 272 + lsl * 2) = *(uint32_t*)&h01;
                *(uint32_t*)(sm + FA_PLO + ltA * 272 + lsl * 2) = *(uint32_t*)&l01;
                *(uint32_t*)(sm + FA_PHI + (ltA + 8) * 272 + lsl * 2) = *(uint32_t*)&h23;
                *(uint32_t*)(sm + FA_PLO + (ltA + 8) * 272 + lsl * 2) = *(uint32_t*)&l23;
            }
        }
        __syncthreads();

        // P @ V : cacc += P(128x128) @ Vt^T(64x128)
        {
            uint32_t phi = sb + FA_PHI, vhi = sb + FA_VHI;
            const int ar  = mr0 + (lane & 15);
            const int bnv = wq * 16 + ((lane >> 4) << 3) + (lane & 7);
            #pragma unroll
            for (int kk = 0; kk < 128; kk += 16) {
                const int akb = (kk + ((lane >> 4) << 3)) * 2;
                const int bkb = (kk + (((lane >> 3) & 1) << 3)) * 2;
                uint32_t Ah[4][4], Al[4][4], Bh[2][2], Bl[2][2];
                #pragma unroll
                for (int i = 0; i < 4; i++) {
                    uint32_t ad = phi + (uint32_t)(ar + i * 16) * 272 + akb;
                    ldm_x4(Ah[i], ad);
                    ldm_x4(Al[i], ad + (FA_PLO - FA_PHI));
                }
                {
                    uint32_t bd = vhi + (uint32_t)bnv * 272 + bkb;
                    uint32_t t[4];
                    ldm_x4(t, bd);
                    Bh[0][0] = t[0]; Bh[0][1] = t[1];
                    Bh[1][0] = t[2]; Bh[1][1] = t[3];
                    ldm_x4(t, bd + (FA_VLO - FA_VHI));
                    Bl[0][0] = t[0]; Bl[0][1] = t[1];
                    Bl[1][0] = t[2]; Bl[1][1] = t[3];
                }
                #pragma unroll
                for (int i = 0; i < 4; i++)
                    #pragma unroll
                    for (int j = 0; j < 2; j++) {
                        mma_bf16(cacc[i*2+j], Ah[i], Bh[j]);
                        mma_bf16(cacc[i*2+j], Ah[i], Bl[j]);
                        mma_bf16(cacc[i*2+j], Al[i], Bh[j]);
                    }
            }
        }
        __syncthreads();
    }

    // ---- write ctx ----
    #pragma unroll
    for (int i = 0; i < 4; i++)
        #pragma unroll
        for (int j = 0; j < 2; j++) {
            int row = bt * 128 + mr0 + i * 16 + (lane >> 2);
            int d = wq * 16 + j * 8 + ((lane & 3) << 1);
            float* p = g_ctx + ((size_t)(b * SEQ + row)) * D_MODEL + h * 64 + d;
            *(float2*)p = make_float2(cacc[i*2+j][0], cacc[i*2+j][1]);
            *(float2*)(p + 8 * D_MODEL) = make_float2(cacc[i*2+j][2], cacc[i*2+j][3]);
        }
}

// ---------------- host helper (defined BEFORE kernel_launch) ----------------
static float* get_attn_fb_ptr()
{
    static float* p = nullptr;
    if (!p) cudaGetSymbolAddress((void**)&p, g_attn_fb);
    return p;
}

// ---------------- launch ------------------------------------------------------
extern "C" void kernel_launch(void* const* d_in, const int* in_sizes, int n_in,
                              void* d_out, int out_size)
{
    const float* query = (const float*)d_in[0];
    const float* key_  = (const float*)d_in[1];
    const float* value = (const float*)d_in[2];
    const float* Wq = (const float*)d_in[3];
    const float* bq = (const float*)d_in[4];
    const float* Wk = (const float*)d_in[5];
    const float* bk = (const float*)d_in[6];
    const float* Wv = (const float*)d_in[7];
    const float* bv = (const float*)d_in[8];
    const float* Wo = (const float*)d_in[9];
    const float* bo = (const float*)d_in[10];
    const float* ln_g = (const float*)d_in[11];
    const float* ln_b = (const float*)d_in[12];

    float* out = (float*)d_out;
    float* attn = ((size_t)out_size >= OUT_ELEMS + ATTN_ELEMS)
                      ? out + OUT_ELEMS : get_attn_fb_ptr();

    cudaFuncSetAttribute(qkv_mma_kernel,    cudaFuncAttributeMaxDynamicSharedMemorySize, PJ_SMEM);
    cudaFuncSetAttribute(oproj_mma_kernel,  cudaFuncAttributeMaxDynamicSharedMemorySize, PJ_SMEM);
    cudaFuncSetAttribute(fused_attn_kernel, cudaFuncAttributeMaxDynamicSharedMemorySize, FA_SMEM);

    ln_kernel<<<dim3(NTOK, 3), 256>>>(query, key_, value, ln_g, ln_b);

    qkv_mma_kernel<<<dim3(D_MODEL / 128, NTOK / 128, 3), 256, PJ_SMEM>>>(
        Wq, bq, Wk, bk, Wv, bv);

    vt_kernel<<<dim3(SEQ / 64, BATCH * NHEAD), 256>>>();

    zerofill_kernel<<<dim3(16, 16, 32), 256>>>(attn);

    fused_attn_kernel<<<dim3(16, 32), 256, FA_SMEM>>>(attn);

    oproj_mma_kernel<<<dim3(D_MODEL / 128, NTOK / 128), 256, PJ_SMEM>>>(Wo, bo, out);
}